// round 14
// baseline (speedup 1.0000x reference)
#include <cuda_runtime.h>
#include <cuda_bf16.h>
#include <cstdint>

// ---------------------------------------------------------------------------
// Problem constants (shapes fixed by setup_inputs)
// ---------------------------------------------------------------------------
#define BB   64          // batch
#define MM   80          // input channels
#define TT_  2000        // time
#define CC   256         // conv out channels
#define HH   256         // hidden
#define KK_  5           // conv kernel
#define TC   1996        // T - K + 1
#define G3H  768         // 3*H
#define NCTA 128         // persistent scan CTAs (16 groups x 8)

typedef unsigned long long u64t;

// ---------------------------------------------------------------------------
// Static device scratch (no runtime allocation allowed)
// ---------------------------------------------------------------------------
__device__ float d_seq[(size_t)TC * BB * CC];            // (Tc,B,C)
__device__ float d_xg[2ull * TC * BB * G3H];             // (dir,Tc,B,3H)
__device__ float d_enc[(size_t)TC * BB * 2 * HH];        // (Tc,B,2H) — doubles as h[t]
__device__ float d_pT[(size_t)BB * 2 * TC];              // (b,o,t)
__device__ float d_wTconv[400 * 256];                    // (m*5+k, c)
__device__ float d_wTih[256 * 1536];                     // (k, dir*768+n)
__device__ float d_bih[1536];
// per-group arrival counter, each group on its own 128B line
__device__ unsigned d_gcnt[16][32];

// ---------------------------------------------------------------------------
// f32x2 packed-FMA helpers (SASS FFMA2 — only reachable via PTX)
// ---------------------------------------------------------------------------
__device__ __forceinline__ u64t fma2(u64t a, u64t b, u64t c) {
    u64t d;
    asm("fma.rn.f32x2 %0, %1, %2, %3;" : "=l"(d) : "l"(a), "l"(b), "l"(c));
    return d;
}
__device__ __forceinline__ u64t pk2(float x, float y) {
    u64t r;
    asm("mov.b64 %0, {%1, %2};" : "=l"(r) : "f"(x), "f"(y));
    return r;
}
__device__ __forceinline__ float2 unpk2(u64t a) {
    float2 v;
    asm("mov.b64 {%0, %1}, %2;" : "=f"(v.x), "=f"(v.y) : "l"(a));
    return v;
}

__device__ __forceinline__ float sigf(float x)  { return 1.f / (1.f + __expf(-x)); }
__device__ __forceinline__ float tanhfast(float x) { return 1.f - 2.f / (__expf(2.f * x) + 1.f); }

// ---------------------------------------------------------------------------
// Kernel 0: weight repack (transposed B matrices), bias pack, state reset
// ---------------------------------------------------------------------------
__global__ void prep_kernel(const float* __restrict__ conv_w,
                            const float* __restrict__ w_ih_f,
                            const float* __restrict__ w_ih_r,
                            const float* __restrict__ b_ih_f,
                            const float* __restrict__ b_ih_r) {
    int i = blockIdx.x * blockDim.x + threadIdx.x;
    int stride = gridDim.x * blockDim.x;
    for (int idx = i; idx < 400 * 256; idx += stride) {
        int mk = idx >> 8, c = idx & 255;
        d_wTconv[idx] = conv_w[c * 400 + mk];
    }
    for (int idx = i; idx < 256 * 1536; idx += stride) {
        int k = idx / 1536, n = idx - k * 1536;
        d_wTih[idx] = (n < 768) ? w_ih_f[n * 256 + k] : w_ih_r[(n - 768) * 256 + k];
    }
    for (int idx = i; idx < 1536; idx += stride)
        d_bih[idx] = (idx < 768) ? b_ih_f[idx] : b_ih_r[idx - 768];
    // reset group barrier counters (graph replays re-run this)
    unsigned* c0 = &d_gcnt[0][0];
    for (int idx = i; idx < 16 * 32; idx += stride) c0[idx] = 0u;
}

// ---------------------------------------------------------------------------
// Kernel 1: conv1d (valid) + ReLU as implicit-im2col GEMM.
// ---------------------------------------------------------------------------
__global__ void __launch_bounds__(256, 2) conv_gemm(const float* __restrict__ x,
                                                    const float* __restrict__ conv_b) {
    __shared__ float As[2][8][128];
    __shared__ float Bs[2][8][128];
    const int tid  = threadIdx.x;
    const int t0   = blockIdx.x * 128;
    const int col0 = blockIdx.y * 128;
    const int b    = blockIdx.z;
    const int tx = tid & 15, ty = tid >> 4;
    const int bk_ = tid >> 5, bc_ = (tid & 31) * 4;
    const float* xb = x + (size_t)b * MM * TT_;

    u64t acc[8][4];
#pragma unroll
    for (int ii = 0; ii < 8; ++ii)
#pragma unroll
        for (int jj = 0; jj < 4; ++jj) acc[ii][jj] = 0ull;

    float aR[4];
    float4 bR;
#pragma unroll
    for (int r2 = 0; r2 < 4; ++r2) {
        int idx = tid + 256 * r2;
        int kc = idx >> 7, tl = idx & 127;
        int m = kc / 5, kq = kc - m * 5;
        int tt = t0 + tl + kq;
        aR[r2] = (tt < TT_) ? xb[m * TT_ + tt] : 0.f;
    }
    bR = *(const float4*)(d_wTconv + (size_t)bk_ * 256 + col0 + bc_);

    int sb = 0;
#pragma unroll
    for (int r2 = 0; r2 < 4; ++r2) {
        int idx = tid + 256 * r2;
        As[sb][idx >> 7][idx & 127] = aR[r2];
    }
    *(float4*)&Bs[sb][bk_][bc_] = bR;
    __syncthreads();

    for (int k0 = 0; k0 < 400; k0 += 8) {
        if (k0 + 8 < 400) {
#pragma unroll
            for (int r2 = 0; r2 < 4; ++r2) {
                int idx = tid + 256 * r2;
                int kc = idx >> 7, tl = idx & 127;
                int mk = k0 + 8 + kc;
                int m = mk / 5, kq = mk - m * 5;
                int tt = t0 + tl + kq;
                aR[r2] = (tt < TT_) ? xb[m * TT_ + tt] : 0.f;
            }
            bR = *(const float4*)(d_wTconv + (size_t)(k0 + 8 + bk_) * 256 + col0 + bc_);
        }
#pragma unroll
        for (int kc = 0; kc < 8; ++kc) {
            float4 a0 = *(const float4*)&As[sb][kc][ty * 8];
            float4 a1 = *(const float4*)&As[sb][kc][ty * 8 + 4];
            const u64t* bp = (const u64t*)&Bs[sb][kc][tx * 8];
            u64t b0 = bp[0], b1 = bp[1], b2 = bp[2], b3 = bp[3];
            float av[8] = {a0.x, a0.y, a0.z, a0.w, a1.x, a1.y, a1.z, a1.w};
#pragma unroll
            for (int ii = 0; ii < 8; ++ii) {
                u64t ad = pk2(av[ii], av[ii]);
                acc[ii][0] = fma2(ad, b0, acc[ii][0]);
                acc[ii][1] = fma2(ad, b1, acc[ii][1]);
                acc[ii][2] = fma2(ad, b2, acc[ii][2]);
                acc[ii][3] = fma2(ad, b3, acc[ii][3]);
            }
        }
        if (k0 + 8 < 400) {
            sb ^= 1;
#pragma unroll
            for (int r2 = 0; r2 < 4; ++r2) {
                int idx = tid + 256 * r2;
                As[sb][idx >> 7][idx & 127] = aR[r2];
            }
            *(float4*)&Bs[sb][bk_][bc_] = bR;
        }
        __syncthreads();
    }

#pragma unroll
    for (int ii = 0; ii < 8; ++ii) {
        int trow = t0 + ty * 8 + ii;
        if (trow >= TC) continue;
        float* op = d_seq + ((size_t)trow * BB + b) * CC + col0 + tx * 8;
#pragma unroll
        for (int jj = 0; jj < 4; ++jj) {
            float2 v = unpk2(acc[ii][jj]);
            int c = col0 + tx * 8 + jj * 2;
            float v0 = v.x + conv_b[c];
            float v1 = v.y + conv_b[c + 1];
            op[jj * 2]     = v0 > 0.f ? v0 : 0.f;
            op[jj * 2 + 1] = v1 > 0.f ? v1 : 0.f;
        }
    }
}

// ---------------------------------------------------------------------------
// Kernel 2: input projections for BOTH directions as one SGEMM.
// ---------------------------------------------------------------------------
__global__ void __launch_bounds__(256, 2) proj_gemm() {
    __shared__ float As[2][8][128];
    __shared__ float Bs[2][8][128];
    const int tid = threadIdx.x;
    const size_t row0 = (size_t)blockIdx.x * 128;
    const int col0 = blockIdx.y * 128;
    const int tx = tid & 15, ty = tid >> 4;
    const int ar_ = tid >> 1, ak_ = (tid & 1) * 4;
    const int bk_ = tid >> 5, bc_ = (tid & 31) * 4;

    const float* Aptr = d_seq + (row0 + ar_) * CC + ak_;
    const float* Bptr = d_wTih + (size_t)bk_ * 1536 + col0 + bc_;

    u64t acc[8][4];
#pragma unroll
    for (int ii = 0; ii < 8; ++ii)
#pragma unroll
        for (int jj = 0; jj < 4; ++jj) acc[ii][jj] = 0ull;

    float4 aR = *(const float4*)(Aptr);
    float4 bR = *(const float4*)(Bptr);

    int sb = 0;
    As[sb][ak_ + 0][ar_] = aR.x;
    As[sb][ak_ + 1][ar_] = aR.y;
    As[sb][ak_ + 2][ar_] = aR.z;
    As[sb][ak_ + 3][ar_] = aR.w;
    *(float4*)&Bs[sb][bk_][bc_] = bR;
    __syncthreads();

    for (int k0 = 0; k0 < 256; k0 += 8) {
        if (k0 + 8 < 256) {
            aR = *(const float4*)(Aptr + (k0 + 8));
            bR = *(const float4*)(Bptr + (size_t)(k0 + 8) * 1536);
        }
#pragma unroll
        for (int kc = 0; kc < 8; ++kc) {
            float4 a0 = *(const float4*)&As[sb][kc][ty * 8];
            float4 a1 = *(const float4*)&As[sb][kc][ty * 8 + 4];
            const u64t* bp = (const u64t*)&Bs[sb][kc][tx * 8];
            u64t b0 = bp[0], b1 = bp[1], b2 = bp[2], b3 = bp[3];
            float av[8] = {a0.x, a0.y, a0.z, a0.w, a1.x, a1.y, a1.z, a1.w};
#pragma unroll
            for (int ii = 0; ii < 8; ++ii) {
                u64t ad = pk2(av[ii], av[ii]);
                acc[ii][0] = fma2(ad, b0, acc[ii][0]);
                acc[ii][1] = fma2(ad, b1, acc[ii][1]);
                acc[ii][2] = fma2(ad, b2, acc[ii][2]);
                acc[ii][3] = fma2(ad, b3, acc[ii][3]);
            }
        }
        if (k0 + 8 < 256) {
            sb ^= 1;
            As[sb][ak_ + 0][ar_] = aR.x;
            As[sb][ak_ + 1][ar_] = aR.y;
            As[sb][ak_ + 2][ar_] = aR.z;
            As[sb][ak_ + 3][ar_] = aR.w;
            *(float4*)&Bs[sb][bk_][bc_] = bR;
        }
        __syncthreads();
    }

    const int dircol = (col0 >= 768) ? 1 : 0;
    float* outbase = d_xg + (size_t)dircol * ((size_t)TC * BB * G3H);
    const int cadj = col0 - dircol * 768 + tx * 8;
#pragma unroll
    for (int ii = 0; ii < 8; ++ii) {
        size_t row = row0 + ty * 8 + ii;
        float* op = outbase + row * G3H + cadj;
#pragma unroll
        for (int jj = 0; jj < 4; ++jj) {
            float2 v = unpk2(acc[ii][jj]);
            int n = col0 + tx * 8 + jj * 2;
            op[jj * 2]     = v.x + d_bih[n];
            op[jj * 2 + 1] = v.y + d_bih[n + 1];
        }
    }
}

// ---------------------------------------------------------------------------
// Kernel 3: persistent bidirectional GRU scan, 16 independent groups of 8
// CTAs. Group = (dir, bblk); member = jblk. Rotation tree-reduce; LDS.128
// h loads. Leader-only acquire poll (8 readers/line, REDG lands promptly);
// xg stash moved after the release to shorten the inter-CTA tail.
// ---------------------------------------------------------------------------
__global__ void __launch_bounds__(256, 1)
scan_kernel(const float* __restrict__ whh_f,
            const float* __restrict__ whh_r,
            const float* __restrict__ bhh_f,
            const float* __restrict__ bhh_r) {
    const int cta  = blockIdx.x;
    const int dir  = cta >> 6;
    const int rem  = cta & 63;
    const int jblk = rem >> 3, bblk = rem & 7;
    const int grp  = dir * 8 + bblk;
    const int tid  = threadIdx.x;
    const int w = tid >> 5, lane = tid & 31;
    const int kk = lane >> 2, jsub = lane & 3;
    const int hl  = w * 4 + jsub;          // hidden-local 0..31
    const int hid = jblk * 32 + hl;        // hidden-global 0..255

    const float* whh = dir ? whh_r : whh_f;
    const float* bhh = dir ? bhh_r : bhh_f;

    // w_hh slice into registers as f32x2 pairs (3 gates x 32 k = 96 floats)
    u64t wr2[16], wz2[16], wn2[16];
    {
        const u64t* pr = (const u64t*)(whh + (size_t)hid * HH + kk * 32);
        const u64t* pz = (const u64t*)(whh + (size_t)(256 + hid) * HH + kk * 32);
        const u64t* pn = (const u64t*)(whh + (size_t)(512 + hid) * HH + kk * 32);
#pragma unroll
        for (int i = 0; i < 16; ++i) { wr2[i] = pr[i]; wz2[i] = pz[i]; wn2[i] = pn[i]; }
    }
    const float bhr = bhh[hid], bhz = bhh[256 + hid], bhn = bhh[512 + hid];

    __shared__ __align__(16) float hs[2304];   // 8 b * 8 chunks * 36 (padded)
    __shared__ float xgs[2][800];               // double-buffered xg stage, stride 100

    const size_t xg_dir = (size_t)dir * ((size_t)TC * BB * G3H);

    // thread's 3 xg elements: e = tid + 256*q; global (eb,er); smem slot xo
    int eb[3], er[3], xo[3];
#pragma unroll
    for (int q = 0; q < 3; ++q) {
        int e = tid + 256 * q;
        eb[q] = e / 96;
        int r2 = e - eb[q] * 96;
        er[q] = (r2 >> 5) * 256 + jblk * 32 + (r2 & 31);
        xo[q] = eb[q] * 100 + r2;
    }
#pragma unroll
    for (int q = 0; q < 3; ++q)
        xgs[0][xo[q]] =
            d_xg[xg_dir + ((size_t)0 * BB + bblk * 8 + eb[q]) * G3H + er[q]];

    // h0 = 0: fill hs once before the loop
    for (int i = tid; i < 2304; i += 256) hs[i] = 0.f;
    __syncthreads();

    unsigned* gcnt = &d_gcnt[grp][0];
    // this lane's per-step constants (batch = kk, hidden = hl/hid)
    const int xg_ir      = kk * 100 + hl;
    const int hprev_slot = kk * 288 + jblk * 36 + hl;
    float* enc_row_base = &d_enc[((size_t)bblk * 8 + kk) * (2 * HH) + dir * HH + hid];

    for (int t = 0; t < TC; ++t) {
        const int buf = t & 1;

        // prefetch next step's xg (LDGs in flight during the poll)
        float pf0 = 0.f, pf1 = 0.f, pf2 = 0.f;
        if (t + 1 < TC) {
            size_t base = xg_dir + ((size_t)(t + 1) * BB + bblk * 8) * G3H;
            pf0 = d_xg[base + (size_t)eb[0] * G3H + er[0]];
            pf1 = d_xg[base + (size_t)eb[1] * G3H + er[1]];
            pf2 = d_xg[base + (size_t)eb[2] * G3H + er[2]];
        }

        if (t > 0) {
            // leader-only acquire poll: 8 readers per flag line, so the
            // producers' red.release RMWs aren't queued behind reader floods
            if (tid == 0) {
                unsigned tgt = (unsigned)t * 8u;
                unsigned v;
                do {
                    asm volatile("ld.acquire.gpu.global.u32 %0, [%1];"
                                 : "=r"(v) : "l"(gcnt) : "memory");
                } while (v < tgt);
            }
            __syncthreads();

            // stage h[t-1] from d_enc into padded smem
            {
                const float* hsrc =
                    &d_enc[((size_t)(t - 1) * BB + bblk * 8) * (2 * HH) + dir * HH];
                int L = tid * 8;
                int bl = L >> 8, k = L & 255;
                float4 v0 = __ldcg((const float4*)(hsrc + bl * 512 + k));
                float4 v1 = __ldcg((const float4*)(hsrc + bl * 512 + k + 4));
                float* dst = &hs[bl * 288 + (k >> 5) * 36 + (k & 31)];
                *(float4*)dst = v0;
                *(float4*)(dst + 4) = v1;
            }
            __syncthreads();
        }

        // ---- batch loop: P[j] = partial(chunk kk, batch kk^j) ----
        float PR[8], PZ[8], PN[8];
#pragma unroll
        for (int j = 0; j < 8; ++j) {
            const int b = kk ^ j;
            const ulonglong2* hp = (const ulonglong2*)&hs[b * 288 + kk * 36];
            u64t ar = 0ull, az = 0ull, an = 0ull;
#pragma unroll
            for (int i = 0; i < 8; ++i) {
                ulonglong2 h2 = hp[i];
                ar = fma2(wr2[2 * i],     h2.x, ar);
                az = fma2(wz2[2 * i],     h2.x, az);
                an = fma2(wn2[2 * i],     h2.x, an);
                ar = fma2(wr2[2 * i + 1], h2.y, ar);
                az = fma2(wz2[2 * i + 1], h2.y, az);
                an = fma2(wn2[2 * i + 1], h2.y, an);
            }
            float2 fr = unpk2(ar), fz = unpk2(az), fn = unpk2(an);
            PR[j] = fr.x + fr.y;
            PZ[j] = fz.x + fz.y;
            PN[j] = fn.x + fn.y;
        }

        // ---- rotation tree-reduce: 3 levels, compile-time indices ----
        PR[0] += __shfl_xor_sync(0xffffffffu, PR[1], 4);
        PZ[0] += __shfl_xor_sync(0xffffffffu, PZ[1], 4);
        PN[0] += __shfl_xor_sync(0xffffffffu, PN[1], 4);
        PR[2] += __shfl_xor_sync(0xffffffffu, PR[3], 4);
        PZ[2] += __shfl_xor_sync(0xffffffffu, PZ[3], 4);
        PN[2] += __shfl_xor_sync(0xffffffffu, PN[3], 4);
        PR[4] += __shfl_xor_sync(0xffffffffu, PR[5], 4);
        PZ[4] += __shfl_xor_sync(0xffffffffu, PZ[5], 4);
        PN[4] += __shfl_xor_sync(0xffffffffu, PN[5], 4);
        PR[6] += __shfl_xor_sync(0xffffffffu, PR[7], 4);
        PZ[6] += __shfl_xor_sync(0xffffffffu, PZ[7], 4);
        PN[6] += __shfl_xor_sync(0xffffffffu, PN[7], 4);
        PR[0] += __shfl_xor_sync(0xffffffffu, PR[2], 8);
        PZ[0] += __shfl_xor_sync(0xffffffffu, PZ[2], 8);
        PN[0] += __shfl_xor_sync(0xffffffffu, PN[2], 8);
        PR[4] += __shfl_xor_sync(0xffffffffu, PR[6], 8);
        PZ[4] += __shfl_xor_sync(0xffffffffu, PZ[6], 8);
        PN[4] += __shfl_xor_sync(0xffffffffu, PN[6], 8);
        PR[0] += __shfl_xor_sync(0xffffffffu, PR[4], 16);
        PZ[0] += __shfl_xor_sync(0xffffffffu, PZ[4], 16);
        PN[0] += __shfl_xor_sync(0xffffffffu, PN[4], 16);

        // ---- gates once per lane (batch kk, hidden hl) ----
        {
            float ir  = xgs[buf][xg_ir];
            float iz  = xgs[buf][xg_ir + 32];
            float inn = xgs[buf][xg_ir + 64];
            float r = sigf(ir + PR[0] + bhr);
            float z = sigf(iz + PZ[0] + bhz);
            float n = tanhfast(inn + r * (PN[0] + bhn));
            float hprev = hs[hprev_slot];
            float hnew = n + z * (hprev - n);
            enc_row_base[(size_t)t * (BB * 2 * HH)] = hnew;
        }

        __syncthreads();   // all CTA h stores issued before arrival
        if (tid == 0) {
            // release-reduction: orders prior stores, no return trip
            asm volatile("red.release.gpu.global.add.u32 [%0], %1;"
                         :: "l"(gcnt), "r"(1u) : "memory");
        }

        // stash prefetched xg into the other buffer (CTA-local — off the
        // inter-CTA critical path; next step's staging sync orders readers)
        if (t + 1 < TC) {
            xgs[buf ^ 1][xo[0]] = pf0;
            xgs[buf ^ 1][xo[1]] = pf1;
            xgs[buf ^ 1][xo[2]] = pf2;
        }
    }
}

// ---------------------------------------------------------------------------
// Kernel 4: classifier projection p[b][o][t] = enc[t][b][:] . clf_w[o][:]
// ---------------------------------------------------------------------------
__global__ void clf_kernel(const float* __restrict__ clf_w) {
    int gw = blockIdx.x * 8 + (threadIdx.x >> 5);
    int lane = threadIdx.x & 31;
    if (gw >= TC * BB) return;
    const float* e = d_enc + (size_t)gw * (2 * HH);
    float s0 = 0.f, s1 = 0.f;
#pragma unroll
    for (int i = 0; i < 16; ++i) {
        float v = e[lane + 32 * i];
        s0 = fmaf(v, clf_w[lane + 32 * i], s0);
        s1 = fmaf(v, clf_w[512 + lane + 32 * i], s1);
    }
#pragma unroll
    for (int off = 16; off >= 1; off >>= 1) {
        s0 += __shfl_xor_sync(0xffffffffu, s0, off);
        s1 += __shfl_xor_sync(0xffffffffu, s1, off);
    }
    if (lane == 0) {
        int t = gw >> 6, b = gw & 63;
        d_pT[((size_t)b * 2 + 0) * TC + t] = s0;
        d_pT[((size_t)b * 2 + 1) * TC + t] = s1;
    }
}

// ---------------------------------------------------------------------------
// Kernel 5: sliding-window mean + bias -> output (Tout,1,B,2)
// ---------------------------------------------------------------------------
__global__ void win_kernel(const float* __restrict__ clf_b, float* __restrict__ out,
                           int Tout, int W, float invW) {
    __shared__ float pr[TC];
    int bo = blockIdx.x;
    int b = bo >> 1, o = bo & 1;
    for (int i = threadIdx.x; i < TC; i += blockDim.x)
        pr[i] = d_pT[(size_t)bo * TC + i];
    __syncthreads();
    float cb = clf_b[o];
    for (int tp = threadIdx.x; tp < Tout; tp += blockDim.x) {
        float s = 0.f;
        for (int i = 0; i < W; ++i) s += pr[tp + i];
        out[((size_t)tp * BB + b) * 2 + o] = s * invW + cb;
    }
}

// ---------------------------------------------------------------------------
// Launch
// ---------------------------------------------------------------------------
extern "C" void kernel_launch(void* const* d_in, const int* in_sizes, int n_in,
                              void* d_out, int out_size) {
    const float* x      = (const float*)d_in[0];
    const float* conv_w = (const float*)d_in[1];
    const float* conv_b = (const float*)d_in[2];
    const float* w_ih_f = (const float*)d_in[3];
    const float* w_hh_f = (const float*)d_in[4];
    const float* b_ih_f = (const float*)d_in[5];
    const float* b_hh_f = (const float*)d_in[6];
    const float* w_ih_r = (const float*)d_in[7];
    const float* w_hh_r = (const float*)d_in[8];
    const float* b_ih_r = (const float*)d_in[9];
    const float* b_hh_r = (const float*)d_in[10];
    const float* clf_w  = (const float*)d_in[11];
    const float* clf_b  = (const float*)d_in[12];
    (void)in_sizes; (void)n_in;

    int Tout = out_size / (BB * 2);   // 1901
    int W = TC - Tout + 1;            // 96

    prep_kernel<<<256, 256>>>(conv_w, w_ih_f, w_ih_r, b_ih_f, b_ih_r);

    dim3 cg(16, 2, BB);
    conv_gemm<<<cg, 256>>>(x, conv_b);

    dim3 pg((TC * BB) / 128, 1536 / 128);
    proj_gemm<<<pg, 256>>>();

    scan_kernel<<<NCTA, 256>>>(w_hh_f, w_hh_r, b_hh_f, b_hh_r);

    clf_kernel<<<(TC * BB) / 8, 256>>>(clf_w);

    win_kernel<<<BB * 2, 256>>>(clf_b, (float*)d_out, Tout, W, 1.f / (float)W);
}

// round 15
// speedup vs baseline: 1.0393x; 1.0393x over previous
#include <cuda_runtime.h>
#include <cuda_bf16.h>
#include <cstdint>

// ---------------------------------------------------------------------------
// Problem constants (shapes fixed by setup_inputs)
// ---------------------------------------------------------------------------
#define BB   64          // batch
#define MM   80          // input channels
#define TT_  2000        // time
#define CC   256         // conv out channels
#define HH   256         // hidden
#define KK_  5           // conv kernel
#define TC   1996        // T - K + 1
#define G3H  768         // 3*H
#define NCTA 128         // persistent scan CTAs (16 groups x 8)

typedef unsigned long long u64t;

// ---------------------------------------------------------------------------
// Static device scratch (no runtime allocation allowed)
// ---------------------------------------------------------------------------
__device__ float d_seq[(size_t)TC * BB * CC];            // (Tc,B,C)
__device__ float d_xg[2ull * TC * BB * G3H];             // (dir,Tc,B,3H)
__device__ float d_enc[(size_t)TC * BB * 2 * HH];        // (Tc,B,2H) — doubles as h[t]
__device__ float d_pT[(size_t)BB * 2 * TC];              // (b,o,t)
__device__ float d_wTconv[400 * 256];                    // (m*5+k, c)
__device__ float d_wTih[256 * 1536];                     // (k, dir*768+n)
__device__ float d_bih[1536];
// per-group arrival counter, each group on its own 128B line
__device__ unsigned d_gcnt[16][32];

// ---------------------------------------------------------------------------
// f32x2 packed-FMA helpers (SASS FFMA2 — only reachable via PTX)
// ---------------------------------------------------------------------------
__device__ __forceinline__ u64t fma2(u64t a, u64t b, u64t c) {
    u64t d;
    asm("fma.rn.f32x2 %0, %1, %2, %3;" : "=l"(d) : "l"(a), "l"(b), "l"(c));
    return d;
}
__device__ __forceinline__ u64t pk2(float x, float y) {
    u64t r;
    asm("mov.b64 %0, {%1, %2};" : "=l"(r) : "f"(x), "f"(y));
    return r;
}
__device__ __forceinline__ float2 unpk2(u64t a) {
    float2 v;
    asm("mov.b64 {%0, %1}, %2;" : "=f"(v.x), "=f"(v.y) : "l"(a));
    return v;
}

__device__ __forceinline__ float sigf(float x)  { return 1.f / (1.f + __expf(-x)); }
__device__ __forceinline__ float tanhfast(float x) { return 1.f - 2.f / (__expf(2.f * x) + 1.f); }

// ---------------------------------------------------------------------------
// Kernel 0: weight repack (transposed B matrices), bias pack, state reset
// ---------------------------------------------------------------------------
__global__ void prep_kernel(const float* __restrict__ conv_w,
                            const float* __restrict__ w_ih_f,
                            const float* __restrict__ w_ih_r,
                            const float* __restrict__ b_ih_f,
                            const float* __restrict__ b_ih_r) {
    int i = blockIdx.x * blockDim.x + threadIdx.x;
    int stride = gridDim.x * blockDim.x;
    for (int idx = i; idx < 400 * 256; idx += stride) {
        int mk = idx >> 8, c = idx & 255;
        d_wTconv[idx] = conv_w[c * 400 + mk];
    }
    for (int idx = i; idx < 256 * 1536; idx += stride) {
        int k = idx / 1536, n = idx - k * 1536;
        d_wTih[idx] = (n < 768) ? w_ih_f[n * 256 + k] : w_ih_r[(n - 768) * 256 + k];
    }
    for (int idx = i; idx < 1536; idx += stride)
        d_bih[idx] = (idx < 768) ? b_ih_f[idx] : b_ih_r[idx - 768];
    // reset group barrier counters (graph replays re-run this)
    unsigned* c0 = &d_gcnt[0][0];
    for (int idx = i; idx < 16 * 32; idx += stride) c0[idx] = 0u;
}

// ---------------------------------------------------------------------------
// Kernel 1: conv1d (valid) + ReLU as implicit-im2col GEMM.
// ---------------------------------------------------------------------------
__global__ void __launch_bounds__(256, 2) conv_gemm(const float* __restrict__ x,
                                                    const float* __restrict__ conv_b) {
    __shared__ float As[2][8][128];
    __shared__ float Bs[2][8][128];
    const int tid  = threadIdx.x;
    const int t0   = blockIdx.x * 128;
    const int col0 = blockIdx.y * 128;
    const int b    = blockIdx.z;
    const int tx = tid & 15, ty = tid >> 4;
    const int bk_ = tid >> 5, bc_ = (tid & 31) * 4;
    const float* xb = x + (size_t)b * MM * TT_;

    u64t acc[8][4];
#pragma unroll
    for (int ii = 0; ii < 8; ++ii)
#pragma unroll
        for (int jj = 0; jj < 4; ++jj) acc[ii][jj] = 0ull;

    float aR[4];
    float4 bR;
#pragma unroll
    for (int r2 = 0; r2 < 4; ++r2) {
        int idx = tid + 256 * r2;
        int kc = idx >> 7, tl = idx & 127;
        int m = kc / 5, kq = kc - m * 5;
        int tt = t0 + tl + kq;
        aR[r2] = (tt < TT_) ? xb[m * TT_ + tt] : 0.f;
    }
    bR = *(const float4*)(d_wTconv + (size_t)bk_ * 256 + col0 + bc_);

    int sb = 0;
#pragma unroll
    for (int r2 = 0; r2 < 4; ++r2) {
        int idx = tid + 256 * r2;
        As[sb][idx >> 7][idx & 127] = aR[r2];
    }
    *(float4*)&Bs[sb][bk_][bc_] = bR;
    __syncthreads();

    for (int k0 = 0; k0 < 400; k0 += 8) {
        if (k0 + 8 < 400) {
#pragma unroll
            for (int r2 = 0; r2 < 4; ++r2) {
                int idx = tid + 256 * r2;
                int kc = idx >> 7, tl = idx & 127;
                int mk = k0 + 8 + kc;
                int m = mk / 5, kq = mk - m * 5;
                int tt = t0 + tl + kq;
                aR[r2] = (tt < TT_) ? xb[m * TT_ + tt] : 0.f;
            }
            bR = *(const float4*)(d_wTconv + (size_t)(k0 + 8 + bk_) * 256 + col0 + bc_);
        }
#pragma unroll
        for (int kc = 0; kc < 8; ++kc) {
            float4 a0 = *(const float4*)&As[sb][kc][ty * 8];
            float4 a1 = *(const float4*)&As[sb][kc][ty * 8 + 4];
            const u64t* bp = (const u64t*)&Bs[sb][kc][tx * 8];
            u64t b0 = bp[0], b1 = bp[1], b2 = bp[2], b3 = bp[3];
            float av[8] = {a0.x, a0.y, a0.z, a0.w, a1.x, a1.y, a1.z, a1.w};
#pragma unroll
            for (int ii = 0; ii < 8; ++ii) {
                u64t ad = pk2(av[ii], av[ii]);
                acc[ii][0] = fma2(ad, b0, acc[ii][0]);
                acc[ii][1] = fma2(ad, b1, acc[ii][1]);
                acc[ii][2] = fma2(ad, b2, acc[ii][2]);
                acc[ii][3] = fma2(ad, b3, acc[ii][3]);
            }
        }
        if (k0 + 8 < 400) {
            sb ^= 1;
#pragma unroll
            for (int r2 = 0; r2 < 4; ++r2) {
                int idx = tid + 256 * r2;
                As[sb][idx >> 7][idx & 127] = aR[r2];
            }
            *(float4*)&Bs[sb][bk_][bc_] = bR;
        }
        __syncthreads();
    }

#pragma unroll
    for (int ii = 0; ii < 8; ++ii) {
        int trow = t0 + ty * 8 + ii;
        if (trow >= TC) continue;
        float* op = d_seq + ((size_t)trow * BB + b) * CC + col0 + tx * 8;
#pragma unroll
        for (int jj = 0; jj < 4; ++jj) {
            float2 v = unpk2(acc[ii][jj]);
            int c = col0 + tx * 8 + jj * 2;
            float v0 = v.x + conv_b[c];
            float v1 = v.y + conv_b[c + 1];
            op[jj * 2]     = v0 > 0.f ? v0 : 0.f;
            op[jj * 2 + 1] = v1 > 0.f ? v1 : 0.f;
        }
    }
}

// ---------------------------------------------------------------------------
// Kernel 2: input projections for BOTH directions as one SGEMM.
// ---------------------------------------------------------------------------
__global__ void __launch_bounds__(256, 2) proj_gemm() {
    __shared__ float As[2][8][128];
    __shared__ float Bs[2][8][128];
    const int tid = threadIdx.x;
    const size_t row0 = (size_t)blockIdx.x * 128;
    const int col0 = blockIdx.y * 128;
    const int tx = tid & 15, ty = tid >> 4;
    const int ar_ = tid >> 1, ak_ = (tid & 1) * 4;
    const int bk_ = tid >> 5, bc_ = (tid & 31) * 4;

    const float* Aptr = d_seq + (row0 + ar_) * CC + ak_;
    const float* Bptr = d_wTih + (size_t)bk_ * 1536 + col0 + bc_;

    u64t acc[8][4];
#pragma unroll
    for (int ii = 0; ii < 8; ++ii)
#pragma unroll
        for (int jj = 0; jj < 4; ++jj) acc[ii][jj] = 0ull;

    float4 aR = *(const float4*)(Aptr);
    float4 bR = *(const float4*)(Bptr);

    int sb = 0;
    As[sb][ak_ + 0][ar_] = aR.x;
    As[sb][ak_ + 1][ar_] = aR.y;
    As[sb][ak_ + 2][ar_] = aR.z;
    As[sb][ak_ + 3][ar_] = aR.w;
    *(float4*)&Bs[sb][bk_][bc_] = bR;
    __syncthreads();

    for (int k0 = 0; k0 < 256; k0 += 8) {
        if (k0 + 8 < 256) {
            aR = *(const float4*)(Aptr + (k0 + 8));
            bR = *(const float4*)(Bptr + (size_t)(k0 + 8) * 1536);
        }
#pragma unroll
        for (int kc = 0; kc < 8; ++kc) {
            float4 a0 = *(const float4*)&As[sb][kc][ty * 8];
            float4 a1 = *(const float4*)&As[sb][kc][ty * 8 + 4];
            const u64t* bp = (const u64t*)&Bs[sb][kc][tx * 8];
            u64t b0 = bp[0], b1 = bp[1], b2 = bp[2], b3 = bp[3];
            float av[8] = {a0.x, a0.y, a0.z, a0.w, a1.x, a1.y, a1.z, a1.w};
#pragma unroll
            for (int ii = 0; ii < 8; ++ii) {
                u64t ad = pk2(av[ii], av[ii]);
                acc[ii][0] = fma2(ad, b0, acc[ii][0]);
                acc[ii][1] = fma2(ad, b1, acc[ii][1]);
                acc[ii][2] = fma2(ad, b2, acc[ii][2]);
                acc[ii][3] = fma2(ad, b3, acc[ii][3]);
            }
        }
        if (k0 + 8 < 256) {
            sb ^= 1;
            As[sb][ak_ + 0][ar_] = aR.x;
            As[sb][ak_ + 1][ar_] = aR.y;
            As[sb][ak_ + 2][ar_] = aR.z;
            As[sb][ak_ + 3][ar_] = aR.w;
            *(float4*)&Bs[sb][bk_][bc_] = bR;
        }
        __syncthreads();
    }

    const int dircol = (col0 >= 768) ? 1 : 0;
    float* outbase = d_xg + (size_t)dircol * ((size_t)TC * BB * G3H);
    const int cadj = col0 - dircol * 768 + tx * 8;
#pragma unroll
    for (int ii = 0; ii < 8; ++ii) {
        size_t row = row0 + ty * 8 + ii;
        float* op = outbase + row * G3H + cadj;
#pragma unroll
        for (int jj = 0; jj < 4; ++jj) {
            float2 v = unpk2(acc[ii][jj]);
            int n = col0 + tx * 8 + jj * 2;
            op[jj * 2]     = v.x + d_bih[n];
            op[jj * 2 + 1] = v.y + d_bih[n + 1];
        }
    }
}

// ---------------------------------------------------------------------------
// Kernel 3: persistent bidirectional GRU scan, 16 independent groups of 8
// CTAs. Group = (dir, bblk); member = jblk. Rotation tree-reduce; LDS.128
// h loads; all-thread acquire poll (R13 configuration, best measured).
// New in R15: hprev carried in a register (this thread's previous hnew).
// ---------------------------------------------------------------------------
__global__ void __launch_bounds__(256, 1)
scan_kernel(const float* __restrict__ whh_f,
            const float* __restrict__ whh_r,
            const float* __restrict__ bhh_f,
            const float* __restrict__ bhh_r) {
    const int cta  = blockIdx.x;
    const int dir  = cta >> 6;
    const int rem  = cta & 63;
    const int jblk = rem >> 3, bblk = rem & 7;
    const int grp  = dir * 8 + bblk;
    const int tid  = threadIdx.x;
    const int w = tid >> 5, lane = tid & 31;
    const int kk = lane >> 2, jsub = lane & 3;
    const int hl  = w * 4 + jsub;          // hidden-local 0..31
    const int hid = jblk * 32 + hl;        // hidden-global 0..255

    const float* whh = dir ? whh_r : whh_f;
    const float* bhh = dir ? bhh_r : bhh_f;

    // w_hh slice into registers as f32x2 pairs (3 gates x 32 k = 96 floats)
    u64t wr2[16], wz2[16], wn2[16];
    {
        const u64t* pr = (const u64t*)(whh + (size_t)hid * HH + kk * 32);
        const u64t* pz = (const u64t*)(whh + (size_t)(256 + hid) * HH + kk * 32);
        const u64t* pn = (const u64t*)(whh + (size_t)(512 + hid) * HH + kk * 32);
#pragma unroll
        for (int i = 0; i < 16; ++i) { wr2[i] = pr[i]; wz2[i] = pz[i]; wn2[i] = pn[i]; }
    }
    const float bhr = bhh[hid], bhz = bhh[256 + hid], bhn = bhh[512 + hid];

    __shared__ __align__(16) float hs[2304];   // 8 b * 8 chunks * 36 (padded)
    __shared__ float xgs[2][800];               // double-buffered xg stage, stride 100

    const size_t xg_dir = (size_t)dir * ((size_t)TC * BB * G3H);

    // thread's 3 xg elements: e = tid + 256*q; global (eb,er); smem slot xo
    int eb[3], er[3], xo[3];
#pragma unroll
    for (int q = 0; q < 3; ++q) {
        int e = tid + 256 * q;
        eb[q] = e / 96;
        int r2 = e - eb[q] * 96;
        er[q] = (r2 >> 5) * 256 + jblk * 32 + (r2 & 31);
        xo[q] = eb[q] * 100 + r2;
    }
#pragma unroll
    for (int q = 0; q < 3; ++q)
        xgs[0][xo[q]] =
            d_xg[xg_dir + ((size_t)0 * BB + bblk * 8 + eb[q]) * G3H + er[q]];

    // h0 = 0: fill hs once before the loop
    for (int i = tid; i < 2304; i += 256) hs[i] = 0.f;
    __syncthreads();

    unsigned* gcnt = &d_gcnt[grp][0];
    // this lane's per-step constants (batch = kk, hidden = hl/hid)
    const int xg_ir = kk * 100 + hl;
    float* enc_row_base = &d_enc[((size_t)bblk * 8 + kk) * (2 * HH) + dir * HH + hid];

    // hprev register carry: h[t-1] for (batch kk, hid) is exactly this
    // thread's previous hnew (h0 = 0)
    float hprev = 0.f;

    for (int t = 0; t < TC; ++t) {
        const int buf = t & 1;

        // prefetch next step's xg (LDGs in flight during the poll)
        float pf0 = 0.f, pf1 = 0.f, pf2 = 0.f;
        if (t + 1 < TC) {
            size_t base = xg_dir + ((size_t)(t + 1) * BB + bblk * 8) * G3H;
            pf0 = d_xg[base + (size_t)eb[0] * G3H + er[0]];
            pf1 = d_xg[base + (size_t)eb[1] * G3H + er[1]];
            pf2 = d_xg[base + (size_t)eb[2] * G3H + er[2]];
        }

        if (t > 0) {
            // all threads acquire-poll the group counter (8 arrivals/step)
            {
                unsigned tgt = (unsigned)t * 8u;
                unsigned v;
                do {
                    asm volatile("ld.acquire.gpu.global.u32 %0, [%1];"
                                 : "=r"(v) : "l"(gcnt) : "memory");
                } while (v < tgt);
            }

            // stage h[t-1] from d_enc into padded smem
            {
                const float* hsrc =
                    &d_enc[((size_t)(t - 1) * BB + bblk * 8) * (2 * HH) + dir * HH];
                int L = tid * 8;
                int bl = L >> 8, k = L & 255;
                float4 v0 = __ldcg((const float4*)(hsrc + bl * 512 + k));
                float4 v1 = __ldcg((const float4*)(hsrc + bl * 512 + k + 4));
                float* dst = &hs[bl * 288 + (k >> 5) * 36 + (k & 31)];
                *(float4*)dst = v0;
                *(float4*)(dst + 4) = v1;
            }
            __syncthreads();
        }

        // ---- batch loop: P[j] = partial(chunk kk, batch kk^j) ----
        float PR[8], PZ[8], PN[8];
#pragma unroll
        for (int j = 0; j < 8; ++j) {
            const int b = kk ^ j;
            const ulonglong2* hp = (const ulonglong2*)&hs[b * 288 + kk * 36];
            u64t ar = 0ull, az = 0ull, an = 0ull;
#pragma unroll
            for (int i = 0; i < 8; ++i) {
                ulonglong2 h2 = hp[i];
                ar = fma2(wr2[2 * i],     h2.x, ar);
                az = fma2(wz2[2 * i],     h2.x, az);
                an = fma2(wn2[2 * i],     h2.x, an);
                ar = fma2(wr2[2 * i + 1], h2.y, ar);
                az = fma2(wz2[2 * i + 1], h2.y, az);
                an = fma2(wn2[2 * i + 1], h2.y, an);
            }
            float2 fr = unpk2(ar), fz = unpk2(az), fn = unpk2(an);
            PR[j] = fr.x + fr.y;
            PZ[j] = fz.x + fz.y;
            PN[j] = fn.x + fn.y;
        }

        // ---- rotation tree-reduce: 3 levels, compile-time indices ----
        PR[0] += __shfl_xor_sync(0xffffffffu, PR[1], 4);
        PZ[0] += __shfl_xor_sync(0xffffffffu, PZ[1], 4);
        PN[0] += __shfl_xor_sync(0xffffffffu, PN[1], 4);
        PR[2] += __shfl_xor_sync(0xffffffffu, PR[3], 4);
        PZ[2] += __shfl_xor_sync(0xffffffffu, PZ[3], 4);
        PN[2] += __shfl_xor_sync(0xffffffffu, PN[3], 4);
        PR[4] += __shfl_xor_sync(0xffffffffu, PR[5], 4);
        PZ[4] += __shfl_xor_sync(0xffffffffu, PZ[5], 4);
        PN[4] += __shfl_xor_sync(0xffffffffu, PN[5], 4);
        PR[6] += __shfl_xor_sync(0xffffffffu, PR[7], 4);
        PZ[6] += __shfl_xor_sync(0xffffffffu, PZ[7], 4);
        PN[6] += __shfl_xor_sync(0xffffffffu, PN[7], 4);
        PR[0] += __shfl_xor_sync(0xffffffffu, PR[2], 8);
        PZ[0] += __shfl_xor_sync(0xffffffffu, PZ[2], 8);
        PN[0] += __shfl_xor_sync(0xffffffffu, PN[2], 8);
        PR[4] += __shfl_xor_sync(0xffffffffu, PR[6], 8);
        PZ[4] += __shfl_xor_sync(0xffffffffu, PZ[6], 8);
        PN[4] += __shfl_xor_sync(0xffffffffu, PN[6], 8);
        PR[0] += __shfl_xor_sync(0xffffffffu, PR[4], 16);
        PZ[0] += __shfl_xor_sync(0xffffffffu, PZ[4], 16);
        PN[0] += __shfl_xor_sync(0xffffffffu, PN[4], 16);

        // ---- gates once per lane (batch kk, hidden hl) ----
        {
            float ir  = xgs[buf][xg_ir];
            float iz  = xgs[buf][xg_ir + 32];
            float inn = xgs[buf][xg_ir + 64];
            float r = sigf(ir + PR[0] + bhr);
            float z = sigf(iz + PZ[0] + bhz);
            float n = tanhfast(inn + r * (PN[0] + bhn));
            float hnew = n + z * (hprev - n);
            hprev = hnew;
            enc_row_base[(size_t)t * (BB * 2 * HH)] = hnew;
        }

        // stash prefetched xg into the other buffer
        if (t + 1 < TC) {
            xgs[buf ^ 1][xo[0]] = pf0;
            xgs[buf ^ 1][xo[1]] = pf1;
            xgs[buf ^ 1][xo[2]] = pf2;
        }

        __syncthreads();   // all CTA h stores issued before arrival
        if (tid == 0) {
            // release-reduction: orders prior stores, no return trip
            asm volatile("red.release.gpu.global.add.u32 [%0], %1;"
                         :: "l"(gcnt), "r"(1u) : "memory");
        }
    }
}

// ---------------------------------------------------------------------------
// Kernel 4: classifier projection p[b][o][t] = enc[t][b][:] . clf_w[o][:]
// ---------------------------------------------------------------------------
__global__ void clf_kernel(const float* __restrict__ clf_w) {
    int gw = blockIdx.x * 8 + (threadIdx.x >> 5);
    int lane = threadIdx.x & 31;
    if (gw >= TC * BB) return;
    const float* e = d_enc + (size_t)gw * (2 * HH);
    float s0 = 0.f, s1 = 0.f;
#pragma unroll
    for (int i = 0; i < 16; ++i) {
        float v = e[lane + 32 * i];
        s0 = fmaf(v, clf_w[lane + 32 * i], s0);
        s1 = fmaf(v, clf_w[512 + lane + 32 * i], s1);
    }
#pragma unroll
    for (int off = 16; off >= 1; off >>= 1) {
        s0 += __shfl_xor_sync(0xffffffffu, s0, off);
        s1 += __shfl_xor_sync(0xffffffffu, s1, off);
    }
    if (lane == 0) {
        int t = gw >> 6, b = gw & 63;
        d_pT[((size_t)b * 2 + 0) * TC + t] = s0;
        d_pT[((size_t)b * 2 + 1) * TC + t] = s1;
    }
}

// ---------------------------------------------------------------------------
// Kernel 5: sliding-window mean + bias -> output (Tout,1,B,2)
// ---------------------------------------------------------------------------
__global__ void win_kernel(const float* __restrict__ clf_b, float* __restrict__ out,
                           int Tout, int W, float invW) {
    __shared__ float pr[TC];
    int bo = blockIdx.x;
    int b = bo >> 1, o = bo & 1;
    for (int i = threadIdx.x; i < TC; i += blockDim.x)
        pr[i] = d_pT[(size_t)bo * TC + i];
    __syncthreads();
    float cb = clf_b[o];
    for (int tp = threadIdx.x; tp < Tout; tp += blockDim.x) {
        float s = 0.f;
        for (int i = 0; i < W; ++i) s += pr[tp + i];
        out[((size_t)tp * BB + b) * 2 + o] = s * invW + cb;
    }
}

// ---------------------------------------------------------------------------
// Launch
// ---------------------------------------------------------------------------
extern "C" void kernel_launch(void* const* d_in, const int* in_sizes, int n_in,
                              void* d_out, int out_size) {
    const float* x      = (const float*)d_in[0];
    const float* conv_w = (const float*)d_in[1];
    const float* conv_b = (const float*)d_in[2];
    const float* w_ih_f = (const float*)d_in[3];
    const float* w_hh_f = (const float*)d_in[4];
    const float* b_ih_f = (const float*)d_in[5];
    const float* b_hh_f = (const float*)d_in[6];
    const float* w_ih_r = (const float*)d_in[7];
    const float* w_hh_r = (const float*)d_in[8];
    const float* b_ih_r = (const float*)d_in[9];
    const float* b_hh_r = (const float*)d_in[10];
    const float* clf_w  = (const float*)d_in[11];
    const float* clf_b  = (const float*)d_in[12];
    (void)in_sizes; (void)n_in;

    int Tout = out_size / (BB * 2);   // 1901
    int W = TC - Tout + 1;            // 96

    prep_kernel<<<256, 256>>>(conv_w, w_ih_f, w_ih_r, b_ih_f, b_ih_r);

    dim3 cg(16, 2, BB);
    conv_gemm<<<cg, 256>>>(x, conv_b);

    dim3 pg((TC * BB) / 128, 1536 / 128);
    proj_gemm<<<pg, 256>>>();

    scan_kernel<<<NCTA, 256>>>(w_hh_f, w_hh_r, b_hh_f, b_hh_r);

    clf_kernel<<<(TC * BB) / 8, 256>>>(clf_w);

    win_kernel<<<BB * 2, 256>>>(clf_b, (float*)d_out, Tout, W, 1.f / (float)W);
}

// round 17
// speedup vs baseline: 1.0872x; 1.0461x over previous
#include <cuda_runtime.h>
#include <cuda_bf16.h>
#include <mma.h>
#include <cstdint>

using namespace nvcuda;

// ---------------------------------------------------------------------------
// Problem constants (shapes fixed by setup_inputs)
// ---------------------------------------------------------------------------
#define BB   64          // batch
#define MM   80          // input channels
#define TT_  2000        // time
#define CC   256         // conv out channels
#define HH   256         // hidden
#define KK_  5           // conv kernel
#define TC   1996        // T - K + 1
#define G3H  768         // 3*H
#define NCTA 128         // persistent scan CTAs (16 groups x 8)

typedef unsigned long long u64t;

// ---------------------------------------------------------------------------
// Static device scratch (no runtime allocation allowed)
// ---------------------------------------------------------------------------
__device__ float d_seq[(size_t)TC * BB * CC];            // (Tc,B,C)
__device__ float d_xg[2ull * TC * BB * G3H];             // (dir,Tc,B,3H) raw (no bias)
__device__ float d_enc[(size_t)TC * BB * 2 * HH];        // (Tc,B,2H) — doubles as h[t]
__device__ float d_pT[(size_t)BB * 2 * TC];              // (b,o,t)
__device__ float d_wTconv[400 * 256];                    // (m*5+k, c)
__device__ float d_bih[1536];                            // folded into scan biases
// bf16 split operands for the WMMA projection GEMM
__device__ __nv_bfloat16 d_Ahi[(size_t)TC * BB * CC];
__device__ __nv_bfloat16 d_Alo[(size_t)TC * BB * CC];
__device__ __nv_bfloat16 d_Bhi[1536 * 256];
__device__ __nv_bfloat16 d_Blo[1536 * 256];
// per-group arrival counter, each group on its own 128B line
__device__ unsigned d_gcnt[16][32];

// ---------------------------------------------------------------------------
// f32x2 packed-FMA helpers (SASS FFMA2 — only reachable via PTX)
// ---------------------------------------------------------------------------
__device__ __forceinline__ u64t fma2(u64t a, u64t b, u64t c) {
    u64t d;
    asm("fma.rn.f32x2 %0, %1, %2, %3;" : "=l"(d) : "l"(a), "l"(b), "l"(c));
    return d;
}
__device__ __forceinline__ u64t pk2(float x, float y) {
    u64t r;
    asm("mov.b64 %0, {%1, %2};" : "=l"(r) : "f"(x), "f"(y));
    return r;
}
__device__ __forceinline__ float2 unpk2(u64t a) {
    float2 v;
    asm("mov.b64 {%0, %1}, %2;" : "=f"(v.x), "=f"(v.y) : "l"(a));
    return v;
}

__device__ __forceinline__ float sigf(float x)  { return 1.f / (1.f + __expf(-x)); }
__device__ __forceinline__ float tanhfast(float x) { return 1.f - 2.f / (__expf(2.f * x) + 1.f); }

// ---------------------------------------------------------------------------
// Kernel 0: weight repack, bias pack, B bf16 split, state reset
// ---------------------------------------------------------------------------
__global__ void prep_kernel(const float* __restrict__ conv_w,
                            const float* __restrict__ w_ih_f,
                            const float* __restrict__ w_ih_r,
                            const float* __restrict__ b_ih_f,
                            const float* __restrict__ b_ih_r) {
    int i = blockIdx.x * blockDim.x + threadIdx.x;
    int stride = gridDim.x * blockDim.x;
    for (int idx = i; idx < 400 * 256; idx += stride) {
        int mk = idx >> 8, c = idx & 255;
        d_wTconv[idx] = conv_w[c * 400 + mk];
    }
    // B split: rows n (dir-concat), cols k — natural w_ih layout [n][k]
    for (int idx = i; idx < 1536 * 256; idx += stride) {
        int n = idx >> 8, k = idx & 255;
        float v = (n < 768) ? w_ih_f[n * 256 + k] : w_ih_r[(n - 768) * 256 + k];
        __nv_bfloat16 h = __float2bfloat16(v);
        d_Bhi[idx] = h;
        d_Blo[idx] = __float2bfloat16(v - __bfloat162float(h));
    }
    for (int idx = i; idx < 1536; idx += stride)
        d_bih[idx] = (idx < 768) ? b_ih_f[idx] : b_ih_r[idx - 768];
    unsigned* c0 = &d_gcnt[0][0];
    for (int idx = i; idx < 16 * 32; idx += stride) c0[idx] = 0u;
}

// ---------------------------------------------------------------------------
// Kernel 1: conv1d (valid) + ReLU as implicit-im2col GEMM. (unchanged)
// ---------------------------------------------------------------------------
__global__ void __launch_bounds__(256, 2) conv_gemm(const float* __restrict__ x,
                                                    const float* __restrict__ conv_b) {
    __shared__ float As[2][8][128];
    __shared__ float Bs[2][8][128];
    const int tid  = threadIdx.x;
    const int t0   = blockIdx.x * 128;
    const int col0 = blockIdx.y * 128;
    const int b    = blockIdx.z;
    const int tx = tid & 15, ty = tid >> 4;
    const int bk_ = tid >> 5, bc_ = (tid & 31) * 4;
    const float* xb = x + (size_t)b * MM * TT_;

    u64t acc[8][4];
#pragma unroll
    for (int ii = 0; ii < 8; ++ii)
#pragma unroll
        for (int jj = 0; jj < 4; ++jj) acc[ii][jj] = 0ull;

    float aR[4];
    float4 bR;
#pragma unroll
    for (int r2 = 0; r2 < 4; ++r2) {
        int idx = tid + 256 * r2;
        int kc = idx >> 7, tl = idx & 127;
        int m = kc / 5, kq = kc - m * 5;
        int tt = t0 + tl + kq;
        aR[r2] = (tt < TT_) ? xb[m * TT_ + tt] : 0.f;
    }
    bR = *(const float4*)(d_wTconv + (size_t)bk_ * 256 + col0 + bc_);

    int sb = 0;
#pragma unroll
    for (int r2 = 0; r2 < 4; ++r2) {
        int idx = tid + 256 * r2;
        As[sb][idx >> 7][idx & 127] = aR[r2];
    }
    *(float4*)&Bs[sb][bk_][bc_] = bR;
    __syncthreads();

    for (int k0 = 0; k0 < 400; k0 += 8) {
        if (k0 + 8 < 400) {
#pragma unroll
            for (int r2 = 0; r2 < 4; ++r2) {
                int idx = tid + 256 * r2;
                int kc = idx >> 7, tl = idx & 127;
                int mk = k0 + 8 + kc;
                int m = mk / 5, kq = mk - m * 5;
                int tt = t0 + tl + kq;
                aR[r2] = (tt < TT_) ? xb[m * TT_ + tt] : 0.f;
            }
            bR = *(const float4*)(d_wTconv + (size_t)(k0 + 8 + bk_) * 256 + col0 + bc_);
        }
#pragma unroll
        for (int kc = 0; kc < 8; ++kc) {
            float4 a0 = *(const float4*)&As[sb][kc][ty * 8];
            float4 a1 = *(const float4*)&As[sb][kc][ty * 8 + 4];
            const u64t* bp = (const u64t*)&Bs[sb][kc][tx * 8];
            u64t b0 = bp[0], b1 = bp[1], b2 = bp[2], b3 = bp[3];
            float av[8] = {a0.x, a0.y, a0.z, a0.w, a1.x, a1.y, a1.z, a1.w};
#pragma unroll
            for (int ii = 0; ii < 8; ++ii) {
                u64t ad = pk2(av[ii], av[ii]);
                acc[ii][0] = fma2(ad, b0, acc[ii][0]);
                acc[ii][1] = fma2(ad, b1, acc[ii][1]);
                acc[ii][2] = fma2(ad, b2, acc[ii][2]);
                acc[ii][3] = fma2(ad, b3, acc[ii][3]);
            }
        }
        if (k0 + 8 < 400) {
            sb ^= 1;
#pragma unroll
            for (int r2 = 0; r2 < 4; ++r2) {
                int idx = tid + 256 * r2;
                As[sb][idx >> 7][idx & 127] = aR[r2];
            }
            *(float4*)&Bs[sb][bk_][bc_] = bR;
        }
        __syncthreads();
    }

#pragma unroll
    for (int ii = 0; ii < 8; ++ii) {
        int trow = t0 + ty * 8 + ii;
        if (trow >= TC) continue;
        float* op = d_seq + ((size_t)trow * BB + b) * CC + col0 + tx * 8;
#pragma unroll
        for (int jj = 0; jj < 4; ++jj) {
            float2 v = unpk2(acc[ii][jj]);
            int c = col0 + tx * 8 + jj * 2;
            float v0 = v.x + conv_b[c];
            float v1 = v.y + conv_b[c + 1];
            op[jj * 2]     = v0 > 0.f ? v0 : 0.f;
            op[jj * 2 + 1] = v1 > 0.f ? v1 : 0.f;
        }
    }
}

// ---------------------------------------------------------------------------
// Kernel 1b: A split — d_seq fp32 -> (hi, lo) bf16
// ---------------------------------------------------------------------------
__global__ void convertA_kernel() {
    size_t i = (size_t)blockIdx.x * blockDim.x + threadIdx.x;
    size_t stride = (size_t)gridDim.x * blockDim.x;
    const size_t N = (size_t)TC * BB * CC;
    for (; i < N; i += stride) {
        float v = d_seq[i];
        __nv_bfloat16 h = __float2bfloat16(v);
        d_Ahi[i] = h;
        d_Alo[i] = __float2bfloat16(v - __bfloat162float(h));
    }
}

// ---------------------------------------------------------------------------
// Kernel 2: WMMA bf16x3 projection GEMM (HMMA path, arch-portable).
// CTA = 128 rows x 128 cols; 8 warps (4m x 2n); warp = 32x64 (2x4 tiles).
// D = Ahi*Bhi + Ahi*Blo + Alo*Bhi, fp32 accumulate. Bias folded into scan.
// ---------------------------------------------------------------------------
__global__ void __launch_bounds__(256, 1) proj_wmma() {
    const int w  = threadIdx.x >> 5;
    const int wm = w >> 1, wn = w & 1;
    const size_t row0 = (size_t)blockIdx.x * 128 + wm * 32;
    const int    col0 = blockIdx.y * 128 + wn * 64;

    wmma::fragment<wmma::accumulator, 16, 16, 16, float> acc[2][4];
#pragma unroll
    for (int i = 0; i < 2; ++i)
#pragma unroll
        for (int j = 0; j < 4; ++j) wmma::fill_fragment(acc[i][j], 0.f);

#pragma unroll 1
    for (int k0 = 0; k0 < 256; k0 += 16) {
        wmma::fragment<wmma::matrix_a, 16, 16, 16, __nv_bfloat16, wmma::row_major> ah[2], al[2];
        wmma::fragment<wmma::matrix_b, 16, 16, 16, __nv_bfloat16, wmma::col_major> bh[4], bl[4];
#pragma unroll
        for (int i = 0; i < 2; ++i) {
            wmma::load_matrix_sync(ah[i], d_Ahi + (row0 + i * 16) * 256 + k0, 256);
            wmma::load_matrix_sync(al[i], d_Alo + (row0 + i * 16) * 256 + k0, 256);
        }
#pragma unroll
        for (int j = 0; j < 4; ++j) {
            wmma::load_matrix_sync(bh[j], d_Bhi + (size_t)(col0 + j * 16) * 256 + k0, 256);
            wmma::load_matrix_sync(bl[j], d_Blo + (size_t)(col0 + j * 16) * 256 + k0, 256);
        }
#pragma unroll
        for (int i = 0; i < 2; ++i)
#pragma unroll
            for (int j = 0; j < 4; ++j) {
                wmma::mma_sync(acc[i][j], ah[i], bh[j], acc[i][j]);
                wmma::mma_sync(acc[i][j], ah[i], bl[j], acc[i][j]);
                wmma::mma_sync(acc[i][j], al[i], bh[j], acc[i][j]);
            }
    }

    const int dircol = (col0 >= 768) ? 1 : 0;
    float* out = d_xg + (size_t)dircol * ((size_t)TC * BB * G3H)
               + row0 * G3H + (col0 - dircol * 768);
#pragma unroll
    for (int i = 0; i < 2; ++i)
#pragma unroll
        for (int j = 0; j < 4; ++j)
            wmma::store_matrix_sync(out + (size_t)i * 16 * G3H + j * 16,
                                    acc[i][j], G3H, wmma::mem_row_major);
}

// ---------------------------------------------------------------------------
// Kernel 3: persistent bidirectional GRU scan (R15 config; b_ih folded in)
// ---------------------------------------------------------------------------
__global__ void __launch_bounds__(256, 1)
scan_kernel(const float* __restrict__ whh_f,
            const float* __restrict__ whh_r,
            const float* __restrict__ bhh_f,
            const float* __restrict__ bhh_r) {
    const int cta  = blockIdx.x;
    const int dir  = cta >> 6;
    const int rem  = cta & 63;
    const int jblk = rem >> 3, bblk = rem & 7;
    const int grp  = dir * 8 + bblk;
    const int tid  = threadIdx.x;
    const int w = tid >> 5, lane = tid & 31;
    const int kk = lane >> 2, jsub = lane & 3;
    const int hl  = w * 4 + jsub;
    const int hid = jblk * 32 + hl;

    const float* whh = dir ? whh_r : whh_f;
    const float* bhh = dir ? bhh_r : bhh_f;

    u64t wr2[16], wz2[16], wn2[16];
    {
        const u64t* pr = (const u64t*)(whh + (size_t)hid * HH + kk * 32);
        const u64t* pz = (const u64t*)(whh + (size_t)(256 + hid) * HH + kk * 32);
        const u64t* pn = (const u64t*)(whh + (size_t)(512 + hid) * HH + kk * 32);
#pragma unroll
        for (int i = 0; i < 16; ++i) { wr2[i] = pr[i]; wz2[i] = pz[i]; wn2[i] = pn[i]; }
    }
    // fold b_ih into the per-lane gate biases (xg is stored raw)
    const float bhr = bhh[hid]       + d_bih[dir * 768 + hid];
    const float bhz = bhh[256 + hid] + d_bih[dir * 768 + 256 + hid];
    const float bhn = bhh[512 + hid];
    const float bin_ = d_bih[dir * 768 + 512 + hid];   // added outside r*( )

    __shared__ __align__(16) float hs[2304];
    __shared__ float xgs[2][800];

    const size_t xg_dir = (size_t)dir * ((size_t)TC * BB * G3H);

    int eb[3], er[3], xo[3];
#pragma unroll
    for (int q = 0; q < 3; ++q) {
        int e = tid + 256 * q;
        eb[q] = e / 96;
        int r2 = e - eb[q] * 96;
        er[q] = (r2 >> 5) * 256 + jblk * 32 + (r2 & 31);
        xo[q] = eb[q] * 100 + r2;
    }
#pragma unroll
    for (int q = 0; q < 3; ++q)
        xgs[0][xo[q]] =
            d_xg[xg_dir + ((size_t)0 * BB + bblk * 8 + eb[q]) * G3H + er[q]];

    for (int i = tid; i < 2304; i += 256) hs[i] = 0.f;
    __syncthreads();

    unsigned* gcnt = &d_gcnt[grp][0];
    const int xg_ir = kk * 100 + hl;
    float* enc_row_base = &d_enc[((size_t)bblk * 8 + kk) * (2 * HH) + dir * HH + hid];

    float hprev = 0.f;

    for (int t = 0; t < TC; ++t) {
        const int buf = t & 1;

        float pf0 = 0.f, pf1 = 0.f, pf2 = 0.f;
        if (t + 1 < TC) {
            size_t base = xg_dir + ((size_t)(t + 1) * BB + bblk * 8) * G3H;
            pf0 = d_xg[base + (size_t)eb[0] * G3H + er[0]];
            pf1 = d_xg[base + (size_t)eb[1] * G3H + er[1]];
            pf2 = d_xg[base + (size_t)eb[2] * G3H + er[2]];
        }

        if (t > 0) {
            {
                unsigned tgt = (unsigned)t * 8u;
                unsigned v;
                do {
                    asm volatile("ld.acquire.gpu.global.u32 %0, [%1];"
                                 : "=r"(v) : "l"(gcnt) : "memory");
                } while (v < tgt);
            }
            {
                const float* hsrc =
                    &d_enc[((size_t)(t - 1) * BB + bblk * 8) * (2 * HH) + dir * HH];
                int L = tid * 8;
                int bl = L >> 8, k = L & 255;
                float4 v0 = __ldcg((const float4*)(hsrc + bl * 512 + k));
                float4 v1 = __ldcg((const float4*)(hsrc + bl * 512 + k + 4));
                float* dst = &hs[bl * 288 + (k >> 5) * 36 + (k & 31)];
                *(float4*)dst = v0;
                *(float4*)(dst + 4) = v1;
            }
            __syncthreads();
        }

        float PR[8], PZ[8], PN[8];
#pragma unroll
        for (int j = 0; j < 8; ++j) {
            const int b = kk ^ j;
            const ulonglong2* hp = (const ulonglong2*)&hs[b * 288 + kk * 36];
            u64t ar = 0ull, az = 0ull, an = 0ull;
#pragma unroll
            for (int i = 0; i < 8; ++i) {
                ulonglong2 h2 = hp[i];
                ar = fma2(wr2[2 * i],     h2.x, ar);
                az = fma2(wz2[2 * i],     h2.x, az);
                an = fma2(wn2[2 * i],     h2.x, an);
                ar = fma2(wr2[2 * i + 1], h2.y, ar);
                az = fma2(wz2[2 * i + 1], h2.y, az);
                an = fma2(wn2[2 * i + 1], h2.y, an);
            }
            float2 fr = unpk2(ar), fz = unpk2(az), fn = unpk2(an);
            PR[j] = fr.x + fr.y;
            PZ[j] = fz.x + fz.y;
            PN[j] = fn.x + fn.y;
        }

        PR[0] += __shfl_xor_sync(0xffffffffu, PR[1], 4);
        PZ[0] += __shfl_xor_sync(0xffffffffu, PZ[1], 4);
        PN[0] += __shfl_xor_sync(0xffffffffu, PN[1], 4);
        PR[2] += __shfl_xor_sync(0xffffffffu, PR[3], 4);
        PZ[2] += __shfl_xor_sync(0xffffffffu, PZ[3], 4);
        PN[2] += __shfl_xor_sync(0xffffffffu, PN[3], 4);
        PR[4] += __shfl_xor_sync(0xffffffffu, PR[5], 4);
        PZ[4] += __shfl_xor_sync(0xffffffffu, PZ[5], 4);
        PN[4] += __shfl_xor_sync(0xffffffffu, PN[5], 4);
        PR[6] += __shfl_xor_sync(0xffffffffu, PR[7], 4);
        PZ[6] += __shfl_xor_sync(0xffffffffu, PZ[7], 4);
        PN[6] += __shfl_xor_sync(0xffffffffu, PN[7], 4);
        PR[0] += __shfl_xor_sync(0xffffffffu, PR[2], 8);
        PZ[0] += __shfl_xor_sync(0xffffffffu, PZ[2], 8);
        PN[0] += __shfl_xor_sync(0xffffffffu, PN[2], 8);
        PR[4] += __shfl_xor_sync(0xffffffffu, PR[6], 8);
        PZ[4] += __shfl_xor_sync(0xffffffffu, PZ[6], 8);
        PN[4] += __shfl_xor_sync(0xffffffffu, PN[6], 8);
        PR[0] += __shfl_xor_sync(0xffffffffu, PR[4], 16);
        PZ[0] += __shfl_xor_sync(0xffffffffu, PZ[4], 16);
        PN[0] += __shfl_xor_sync(0xffffffffu, PN[4], 16);

        {
            float ir  = xgs[buf][xg_ir];
            float iz  = xgs[buf][xg_ir + 32];
            float inn = xgs[buf][xg_ir + 64];
            float r = sigf(ir + PR[0] + bhr);
            float z = sigf(iz + PZ[0] + bhz);
            float n = tanhfast(inn + bin_ + r * (PN[0] + bhn));
            float hnew = n + z * (hprev - n);
            hprev = hnew;
            enc_row_base[(size_t)t * (BB * 2 * HH)] = hnew;
        }

        if (t + 1 < TC) {
            xgs[buf ^ 1][xo[0]] = pf0;
            xgs[buf ^ 1][xo[1]] = pf1;
            xgs[buf ^ 1][xo[2]] = pf2;
        }

        __syncthreads();
        if (tid == 0) {
            asm volatile("red.release.gpu.global.add.u32 [%0], %1;"
                         :: "l"(gcnt), "r"(1u) : "memory");
        }
    }
}

// ---------------------------------------------------------------------------
// Kernel 4: classifier projection
// ---------------------------------------------------------------------------
__global__ void clf_kernel(const float* __restrict__ clf_w) {
    int gw = blockIdx.x * 8 + (threadIdx.x >> 5);
    int lane = threadIdx.x & 31;
    if (gw >= TC * BB) return;
    const float* e = d_enc + (size_t)gw * (2 * HH);
    float s0 = 0.f, s1 = 0.f;
#pragma unroll
    for (int i = 0; i < 16; ++i) {
        float v = e[lane + 32 * i];
        s0 = fmaf(v, clf_w[lane + 32 * i], s0);
        s1 = fmaf(v, clf_w[512 + lane + 32 * i], s1);
    }
#pragma unroll
    for (int off = 16; off >= 1; off >>= 1) {
        s0 += __shfl_xor_sync(0xffffffffu, s0, off);
        s1 += __shfl_xor_sync(0xffffffffu, s1, off);
    }
    if (lane == 0) {
        int t = gw >> 6, b = gw & 63;
        d_pT[((size_t)b * 2 + 0) * TC + t] = s0;
        d_pT[((size_t)b * 2 + 1) * TC + t] = s1;
    }
}

// ---------------------------------------------------------------------------
// Kernel 5: sliding-window mean + bias -> output (Tout,1,B,2)
// ---------------------------------------------------------------------------
__global__ void win_kernel(const float* __restrict__ clf_b, float* __restrict__ out,
                           int Tout, int W, float invW) {
    __shared__ float pr[TC];
    int bo = blockIdx.x;
    int b = bo >> 1, o = bo & 1;
    for (int i = threadIdx.x; i < TC; i += blockDim.x)
        pr[i] = d_pT[(size_t)bo * TC + i];
    __syncthreads();
    float cb = clf_b[o];
    for (int tp = threadIdx.x; tp < Tout; tp += blockDim.x) {
        float s = 0.f;
        for (int i = 0; i < W; ++i) s += pr[tp + i];
        out[((size_t)tp * BB + b) * 2 + o] = s * invW + cb;
    }
}

// ---------------------------------------------------------------------------
// Launch
// ---------------------------------------------------------------------------
extern "C" void kernel_launch(void* const* d_in, const int* in_sizes, int n_in,
                              void* d_out, int out_size) {
    const float* x      = (const float*)d_in[0];
    const float* conv_w = (const float*)d_in[1];
    const float* conv_b = (const float*)d_in[2];
    const float* w_ih_f = (const float*)d_in[3];
    const float* w_hh_f = (const float*)d_in[4];
    const float* b_ih_f = (const float*)d_in[5];
    const float* b_hh_f = (const float*)d_in[6];
    const float* w_ih_r = (const float*)d_in[7];
    const float* w_hh_r = (const float*)d_in[8];
    const float* b_ih_r = (const float*)d_in[9];
    const float* b_hh_r = (const float*)d_in[10];
    const float* clf_w  = (const float*)d_in[11];
    const float* clf_b  = (const float*)d_in[12];
    (void)in_sizes; (void)n_in;

    int Tout = out_size / (BB * 2);   // 1901
    int W = TC - Tout + 1;            // 96

    prep_kernel<<<256, 256>>>(conv_w, w_ih_f, w_ih_r, b_ih_f, b_ih_r);

    dim3 cg(16, 2, BB);
    conv_gemm<<<cg, 256>>>(x, conv_b);

    convertA_kernel<<<1024, 256>>>();

    dim3 pg((TC * BB) / 128, 1536 / 128);
    proj_wmma<<<pg, 256>>>();

    scan_kernel<<<NCTA, 256>>>(w_hh_f, w_hh_r, b_hh_f, b_hh_r);

    clf_kernel<<<(TC * BB) / 8, 256>>>(clf_w);

    win_kernel<<<BB * 2, 256>>>(clf_b, (float*)d_out, Tout, W, 1.f / (float)W);
}